// round 3
// baseline (speedup 1.0000x reference)
#include <cuda_runtime.h>
#include <math.h>

#define RS2 0.70710678118654752440f   /* 1/sqrt(2) */

// Shapes
#define Tn 4
#define Bn 8
#define Cn 256
#define Hn 32
#define Wn 32
#define BCHW 2097152   /* B*C*H*W */
#define NTOT 8388608   /* T*B*C*H*W */

// ---------------- scratch (device globals; no allocation allowed) ----------------
__device__ float g_xs[NTOT];   // spikes (TB,C,H,W)
__device__ float g_h1[NTOT];   // post-coeff-gate, pre-BN h1 (TB,2C,H,W2)
__device__ float g_h2[NTOT];   // post-coeff-gate, pre-gate/BN h2 (TB,4C,H2,W2)
__device__ float g_rec[NTOT];  // pre-BN rec (TB,C,H,W)
__device__ float g_c1b[NTOT];  // pre-BN conv1 out
__device__ float g_c2b[NTOT];  // pre-BN conv2 out
__device__ float g_aff[4608];  // folded BN affine params
// fwd a:0 b:512 | mul a:1024 b:2048 | inv a:3072 b:3328 | c1 a:3584 b:3840 | c2 a:4096 b:4352

// per-channel (sum, sumsq) partials
__device__ float g_ps_fwd[512 * 8],   g_pq_fwd[512 * 8];
__device__ float g_ps_mul[1024 * 32], g_pq_mul[1024 * 32];
__device__ float g_ps_inv[256 * 32],  g_pq_inv[256 * 32];
__device__ float g_ps_c1[256 * 128],  g_pq_c1[256 * 128];
__device__ float g_ps_c2[256 * 64],   g_pq_c2[256 * 64];

// ---------------- LIF + Haar-W + coeff_gate + fwd-stat partials ----------------
// block = (b, c): one (b,c) spatial plane (1024 elems = 256 float4), all 4 t.
__global__ void lif_h1_kernel(const float4* __restrict__ x4) {
    int blk = blockIdx.x;          // b*256 + c
    int c = blk & 255, b = blk >> 8;
    int tid = threadIdx.x;
    int i4 = blk * 256 + tid;      // float4 index into BCHW/4
    int h  = tid >> 3;
    int w8 = tid & 7;              // float4 group within the row (4 w each)
    float4 v = make_float4(0.f, 0.f, 0.f, 0.f);
    float4* xs4 = (float4*)g_xs;
    float2* h1f2 = (float2*)g_h1;
    float slo = 0.f, qlo = 0.f, shi = 0.f, qhi = 0.f;
#pragma unroll
    for (int t = 0; t < Tn; t++) {
        float4 xt = x4[t * (BCHW / 4) + i4];
        float4 s;
        v.x += (xt.x - v.x) * 0.5f; s.x = (v.x >= 1.0f) ? 1.f : 0.f; v.x *= (1.f - s.x);
        v.y += (xt.y - v.y) * 0.5f; s.y = (v.y >= 1.0f) ? 1.f : 0.f; v.y *= (1.f - s.y);
        v.z += (xt.z - v.z) * 0.5f; s.z = (v.z >= 1.0f) ? 1.f : 0.f; v.z *= (1.f - s.z);
        v.w += (xt.w - v.w) * 0.5f; s.w = (v.w >= 1.0f) ? 1.f : 0.f; v.w *= (1.f - s.w);
        xs4[t * (BCHW / 4) + i4] = s;
        float lo0 = (s.x + s.y) * RS2, hi0 = (s.x - s.y) * RS2;
        float lo1 = (s.z + s.w) * RS2, hi1 = (s.z - s.w) * RS2;
        lo0 = (fabsf(lo0) >= 0.5f) ? lo0 : 0.f;
        lo1 = (fabsf(lo1) >= 0.5f) ? lo1 : 0.f;
        hi0 = (fabsf(hi0) >= 0.5f) ? hi0 : 0.f;
        hi1 = (fabsf(hi1) >= 0.5f) ? hi1 : 0.f;
        int n = t * Bn + b;
        int ob2 = ((n * 512 + c) * Hn + h) * 8 + w8;   // float2 index
        h1f2[ob2]         = make_float2(lo0, lo1);
        h1f2[ob2 + 65536] = make_float2(hi0, hi1);     // +256 channels
        slo += lo0 + lo1; qlo += lo0 * lo0 + lo1 * lo1;
        shi += hi0 + hi1; qhi += hi0 * hi0 + hi1 * hi1;
    }
    // block reduce 4 values
#pragma unroll
    for (int o = 16; o > 0; o >>= 1) {
        slo += __shfl_down_sync(0xffffffffu, slo, o);
        qlo += __shfl_down_sync(0xffffffffu, qlo, o);
        shi += __shfl_down_sync(0xffffffffu, shi, o);
        qhi += __shfl_down_sync(0xffffffffu, qhi, o);
    }
    __shared__ float R[8][4];
    if ((tid & 31) == 0) {
        int w = tid >> 5;
        R[w][0] = slo; R[w][1] = qlo; R[w][2] = shi; R[w][3] = qhi;
    }
    __syncthreads();
    if (tid < 4) {
        float a = 0.f;
#pragma unroll
        for (int w = 0; w < 8; w++) a += R[w][tid];
        if (tid == 0) g_ps_fwd[c * 8 + b] = a;
        else if (tid == 1) g_pq_fwd[c * 8 + b] = a;
        else if (tid == 2) g_ps_fwd[(256 + c) * 8 + b] = a;
        else               g_pq_fwd[(256 + c) * 8 + b] = a;
    }
}

// ---------------- fold partials -> affine params ----------------
__global__ void fold_kernel(const float* __restrict__ ps, const float* __restrict__ pq,
                            int P, float inv_cnt,
                            const float* __restrict__ g, const float* __restrict__ b,
                            float* __restrict__ a_out, float* __restrict__ sh_out, int gated) {
    int c = blockIdx.x * 64 + threadIdx.x;
    float s = 0.f, q = 0.f;
    const float* pp = ps + c * P;
    const float* qq = pq + c * P;
    for (int i = 0; i < P; i++) { s += pp[i]; q += qq[i]; }
    float mean = s * inv_cnt;
    float msq  = q * inv_cnt;
    float var = msq - mean * mean;
    if (var < 0.f) var = 0.f;
    bool on = true;
    if (gated) {
        const float taus[4] = {0.01f, 0.02f, 0.02f, 0.05f};
        on = (msq - taus[c >> 8]) >= 0.f;
    }
    float a, sh;
    if (on) { a = g[c] / sqrtf(var + 1e-5f); sh = b[c] - mean * a; }
    else    { a = 0.f; sh = b[c]; }
    a_out[c] = a;
    sh_out[c] = sh;
}

// ---------------- BN(fwd)-apply + Haar-H + coeff_gate -> h2 + mul-stat partials ----------------
// block = (n, c): one full 16x16 plane.
__global__ void h2_kernel() {
    int blk = blockIdx.x;       // n*256 + c
    int c = blk & 255, n = blk >> 8;
    int tid = threadIdx.x;      // h2*16 + w2
    int h2 = tid >> 4, w2 = tid & 15;
    float aL = g_aff[c],       bL = g_aff[512 + c];
    float aH = g_aff[256 + c], bH = g_aff[768 + c];
    int b0 = ((n * 512 + c) * Hn + 2 * h2) * 16 + w2;
    float L0 = g_h1[b0] * aL + bL;
    float L1 = g_h1[b0 + 16] * aL + bL;
    int bh = b0 + 131072;
    float G0 = g_h1[bh] * aH + bH;
    float G1 = g_h1[bh + 16] * aH + bH;
    float sv[8];
    float LL = (L0 + L1) * RS2, HL = (L0 - L1) * RS2;
    float LH = (G0 + G1) * RS2, HH = (G0 - G1) * RS2;
    LL = (fabsf(LL) >= 0.5f) ? LL : 0.f;
    HL = (fabsf(HL) >= 0.5f) ? HL : 0.f;
    LH = (fabsf(LH) >= 0.5f) ? LH : 0.f;
    HH = (fabsf(HH) >= 0.5f) ? HH : 0.f;
    int ob = (n * 1024 + c) * 256 + tid;
    g_h2[ob]          = LL;
    g_h2[ob + 65536]  = HL;
    g_h2[ob + 131072] = LH;
    g_h2[ob + 196608] = HH;
    sv[0] = LL; sv[1] = LL * LL;
    sv[2] = HL; sv[3] = HL * HL;
    sv[4] = LH; sv[5] = LH * LH;
    sv[6] = HH; sv[7] = HH * HH;
#pragma unroll
    for (int j = 0; j < 8; j++)
#pragma unroll
        for (int o = 16; o > 0; o >>= 1)
            sv[j] += __shfl_down_sync(0xffffffffu, sv[j], o);
    __shared__ float R[8][8];
    if ((tid & 31) == 0) {
        int w = tid >> 5;
#pragma unroll
        for (int j = 0; j < 8; j++) R[w][j] = sv[j];
    }
    __syncthreads();
    if (tid < 8) {
        float a = 0.f;
#pragma unroll
        for (int w = 0; w < 8; w++) a += R[w][tid];
        int band = tid >> 1;
        int idx = (band * 256 + c) * 32 + n;
        if ((tid & 1) == 0) g_ps_mul[idx] = a;
        else                g_pq_mul[idx] = a;
    }
}

// ---------------- gate+BN(mul)-apply + 16x16 mixing + inverse Haar + inv-stat partials ----------------
// block = (n, cg): 16 output channels, all 4 bands, full 16x16 plane.
__global__ void __launch_bounds__(256) mixinv_kernel(const float* __restrict__ hw) {
    int n = blockIdx.x >> 4, cg = blockIdx.x & 15;
    int tid = threadIdx.x;     // h2*16 + w2
    __shared__ float Wsh[4][256];
    __shared__ float Aa[4][16], Ab[4][16];
#pragma unroll
    for (int band = 0; band < 4; band++) {
        int nb = band * 4 + (cg >> 2);
        Wsh[band][tid] = hw[nb * 256 + tid];
    }
    if (tid < 64) {
        int band = tid >> 4, k = tid & 15;
        int ch = band * 256 + cg * 16 + k;
        Aa[band][k] = g_aff[1024 + ch];
        Ab[band][k] = g_aff[2048 + ch];
    }
    __syncthreads();
    float out[4][16];
#pragma unroll
    for (int band = 0; band < 4; band++) {
        const float* ip = g_h2 + (n * 1024 + band * 256 + cg * 16) * 256 + tid;
        float xin[16];
#pragma unroll
        for (int d = 0; d < 16; d++) xin[d] = ip[d * 256] * Aa[band][d] + Ab[band][d];
#pragma unroll
        for (int k = 0; k < 16; k++) {
            float acc = 0.f;
#pragma unroll
            for (int d = 0; d < 16; d++) acc = fmaf(xin[d], Wsh[band][d * 16 + k], acc);
            out[band][k] = acc;
        }
    }
    int h2i = tid >> 4, w2 = tid & 15;
    float sk[16], qk[16];
    float2* rec2 = (float2*)g_rec;
#pragma unroll
    for (int k = 0; k < 16; k++) {
        float A = out[0][k], B = out[1][k], C = out[2][k], D = out[3][k];
        float Lr0 = (A + B) * RS2, Lr1 = (A - B) * RS2;
        float Hr0 = (C + D) * RS2, Hr1 = (C - D) * RS2;
        int c = cg * 16 + k;
        int ob2 = (((n * 256 + c) * Hn + 2 * h2i) * Wn + 2 * w2) >> 1;  // float2 index
        rec2[ob2]      = make_float2((Lr0 + Hr0) * RS2, (Lr0 - Hr0) * RS2);
        rec2[ob2 + 16] = make_float2((Lr1 + Hr1) * RS2, (Lr1 - Hr1) * RS2);
        sk[k] = 2.0f * A;                       // exact sum of the 4 rec values
        qk[k] = A * A + B * B + C * C + D * D;  // exact sumsq (orthogonality)
    }
#pragma unroll
    for (int k = 0; k < 16; k++)
#pragma unroll
        for (int o = 16; o > 0; o >>= 1) {
            sk[k] += __shfl_down_sync(0xffffffffu, sk[k], o);
            qk[k] += __shfl_down_sync(0xffffffffu, qk[k], o);
        }
    __shared__ float R[16][2][8];
    if ((tid & 31) == 0) {
        int w = tid >> 5;
#pragma unroll
        for (int k = 0; k < 16; k++) { R[k][0][w] = sk[k]; R[k][1][w] = qk[k]; }
    }
    __syncthreads();
    if (tid < 32) {
        int k = tid >> 1, j = tid & 1;
        float a = 0.f;
#pragma unroll
        for (int w = 0; w < 8; w++) a += R[k][j][w];
        int idx = (cg * 16 + k) * 32 + n;
        if (j == 0) g_ps_inv[idx] = a;
        else        g_pq_inv[idx] = a;
    }
}

// ---------------- 1x1 conv over 16-channel blocks + c1-stat partials ----------------
__global__ void conv1_kernel(const float* __restrict__ w1, const float* __restrict__ b1) {
    __shared__ float wsh[256];
    __shared__ float bsh[16];
    int tid = threadIdx.x;
    wsh[tid] = w1[tid];           // (k,d,1,1) -> [k*16+d]
    if (tid < 16) bsh[tid] = b1[tid];
    __syncthreads();
    int ns = blockIdx.x >> 2;     // 512 samples
    int part = blockIdx.x & 3;
    int pos = part * 256 + tid;
    const float* xin = g_xs + ns * 16384 + pos;
    float xv[16];
#pragma unroll
    for (int d = 0; d < 16; d++) xv[d] = xin[d * 1024];
    float* op = g_c1b + ns * 16384 + pos;
    float sk[16], qk[16];
#pragma unroll
    for (int k = 0; k < 16; k++) {
        float a = bsh[k];
#pragma unroll
        for (int d = 0; d < 16; d++) a = fmaf(xv[d], wsh[k * 16 + d], a);
        op[k * 1024] = a;
        sk[k] = a; qk[k] = a * a;
    }
#pragma unroll
    for (int k = 0; k < 16; k++)
#pragma unroll
        for (int o = 16; o > 0; o >>= 1) {
            sk[k] += __shfl_down_sync(0xffffffffu, sk[k], o);
            qk[k] += __shfl_down_sync(0xffffffffu, qk[k], o);
        }
    __shared__ float R[16][2][8];
    if ((tid & 31) == 0) {
        int w = tid >> 5;
#pragma unroll
        for (int k = 0; k < 16; k++) { R[k][0][w] = sk[k]; R[k][1][w] = qk[k]; }
    }
    __syncthreads();
    if (tid < 32) {
        int k = tid >> 1, j = tid & 1;
        float a = 0.f;
#pragma unroll
        for (int w = 0; w < 8; w++) a += R[k][j][w];
        int nb = ns & 15, nn = ns >> 4;
        int idx = (nb * 16 + k) * 128 + nn * 4 + part;
        if (j == 0) g_ps_c1[idx] = a;
        else        g_pq_c1[idx] = a;
    }
}

// ---------------- 3x3 SAME conv over 16-channel blocks + c2-stat partials ----------------
__global__ void __launch_bounds__(128) conv2_kernel(const float* __restrict__ w2,
                                                    const float* __restrict__ b2) {
    int blk = blockIdx.x;      // 0..1023
    int ns = blk >> 1;
    int h0 = (blk & 1) * 16;
    extern __shared__ float sm[];
    float* tile = sm;          // 16 * 18 * 34 = 9792 floats
    float* wsh  = sm + 9792;   // 2304 floats
    __shared__ float bsh[16];
    int tid = threadIdx.x;
    for (int i = tid; i < 2304; i += 128) wsh[i] = w2[i];
    if (tid < 16) bsh[tid] = b2[tid];
    const float* xin = g_xs + ns * 16384;
    for (int i = tid; i < 9792; i += 128) {
        int d = i / 612;
        int rem = i - d * 612;
        int row = rem / 34;
        int colp = rem - row * 34;
        int gr = h0 + row - 1, gc = colp - 1;
        float v = 0.f;
        if ((unsigned)gr < 32u && (unsigned)gc < 32u) v = xin[d * 1024 + gr * 32 + gc];
        tile[i] = v;
    }
    __syncthreads();
    int col = tid & 31;
    int r0 = (tid >> 5) * 4;   // 0,4,8,12 within the 16-row tile
    float acc[16][4];
#pragma unroll
    for (int k = 0; k < 16; k++) {
        float bv = bsh[k];
#pragma unroll
        for (int rr = 0; rr < 4; rr++) acc[k][rr] = bv;
    }
    for (int d = 0; d < 16; d++) {
        float xr[6][3];
#pragma unroll
        for (int rr = 0; rr < 6; rr++)
#pragma unroll
            for (int cc = 0; cc < 3; cc++)
                xr[rr][cc] = tile[d * 612 + (r0 + rr) * 34 + col + cc];
#pragma unroll
        for (int k = 0; k < 16; k++) {
            const float* wp = wsh + (k * 16 + d) * 9;
            float w0 = wp[0], w1v = wp[1], w2v = wp[2];
            float w3 = wp[3], w4  = wp[4], w5  = wp[5];
            float w6 = wp[6], w7  = wp[7], w8  = wp[8];
#pragma unroll
            for (int rr = 0; rr < 4; rr++) {
                float a = acc[k][rr];
                a = fmaf(w0, xr[rr][0],     a);
                a = fmaf(w1v, xr[rr][1],    a);
                a = fmaf(w2v, xr[rr][2],    a);
                a = fmaf(w3, xr[rr + 1][0], a);
                a = fmaf(w4, xr[rr + 1][1], a);
                a = fmaf(w5, xr[rr + 1][2], a);
                a = fmaf(w6, xr[rr + 2][0], a);
                a = fmaf(w7, xr[rr + 2][1], a);
                a = fmaf(w8, xr[rr + 2][2], a);
                acc[k][rr] = a;
            }
        }
    }
    float* op = g_c2b + ns * 16384;
    float sk[16], qk[16];
#pragma unroll
    for (int k = 0; k < 16; k++) {
        float s = 0.f, q = 0.f;
#pragma unroll
        for (int rr = 0; rr < 4; rr++) {
            float a = acc[k][rr];
            op[k * 1024 + (h0 + r0 + rr) * 32 + col] = a;
            s += a; q += a * a;
        }
        sk[k] = s; qk[k] = q;
    }
#pragma unroll
    for (int k = 0; k < 16; k++)
#pragma unroll
        for (int o = 16; o > 0; o >>= 1) {
            sk[k] += __shfl_down_sync(0xffffffffu, sk[k], o);
            qk[k] += __shfl_down_sync(0xffffffffu, qk[k], o);
        }
    __shared__ float R[16][2][4];
    if ((tid & 31) == 0) {
        int w = tid >> 5;
#pragma unroll
        for (int k = 0; k < 16; k++) { R[k][0][w] = sk[k]; R[k][1][w] = qk[k]; }
    }
    __syncthreads();
    if (tid < 32) {
        int k = tid >> 1, j = tid & 1;
        float a = 0.f;
#pragma unroll
        for (int w = 0; w < 4; w++) a += R[k][j][w];
        int nb = ns & 15, nn = ns >> 4;
        int idx = (nb * 16 + k) * 64 + nn * 2 + (blk & 1);
        if (j == 0) g_ps_c2[idx] = a;
        else        g_pq_c2[idx] = a;
    }
}

// ---------------- final: BN-apply x3 + sum (float4) ----------------
__global__ void final_kernel(float4* __restrict__ out) {
    int i4 = blockIdx.x * 256 + threadIdx.x;  // over NTOT/4
    int c = (i4 >> 8) & 255;
    float ar = g_aff[3072 + c], br = g_aff[3328 + c];
    float a1 = g_aff[3584 + c], b1 = g_aff[3840 + c];
    float a2 = g_aff[4096 + c], b2 = g_aff[4352 + c];
    float4 r = ((const float4*)g_rec)[i4];
    float4 u = ((const float4*)g_c1b)[i4];
    float4 v = ((const float4*)g_c2b)[i4];
    float4 o;
    o.x = r.x * ar + br + u.x * a1 + b1 + v.x * a2 + b2;
    o.y = r.y * ar + br + u.y * a1 + b1 + v.y * a2 + b2;
    o.z = r.z * ar + br + u.z * a1 + b1 + v.z * a2 + b2;
    o.w = r.w * ar + br + u.w * a1 + b1 + v.w * a2 + b2;
    out[i4] = o;
}

// ---------------- host ----------------
extern "C" void kernel_launch(void* const* d_in, const int* in_sizes, int n_in,
                              void* d_out, int out_size) {
    const float* x    = (const float*)d_in[0];
    const float* hw   = (const float*)d_in[1];
    const float* w1   = (const float*)d_in[2];
    const float* b1   = (const float*)d_in[3];
    const float* w2   = (const float*)d_in[4];
    const float* b2   = (const float*)d_in[5];
    const float* gfwd = (const float*)d_in[6];
    const float* bfwd = (const float*)d_in[7];
    const float* gmul = (const float*)d_in[8];
    const float* bmul = (const float*)d_in[9];
    const float* ginv = (const float*)d_in[10];
    const float* binv = (const float*)d_in[11];
    const float* gc1  = (const float*)d_in[12];
    const float* bc1  = (const float*)d_in[13];
    const float* gc2  = (const float*)d_in[14];
    const float* bc2  = (const float*)d_in[15];
    float* out = (float*)d_out;

    float *affP, *psF, *pqF, *psM, *pqM, *psI, *pqI, *ps1, *pq1, *ps2, *pq2;
    cudaGetSymbolAddress((void**)&affP, g_aff);
    cudaGetSymbolAddress((void**)&psF, g_ps_fwd);
    cudaGetSymbolAddress((void**)&pqF, g_pq_fwd);
    cudaGetSymbolAddress((void**)&psM, g_ps_mul);
    cudaGetSymbolAddress((void**)&pqM, g_pq_mul);
    cudaGetSymbolAddress((void**)&psI, g_ps_inv);
    cudaGetSymbolAddress((void**)&pqI, g_pq_inv);
    cudaGetSymbolAddress((void**)&ps1, g_ps_c1);
    cudaGetSymbolAddress((void**)&pq1, g_pq_c1);
    cudaGetSymbolAddress((void**)&ps2, g_ps_c2);
    cudaGetSymbolAddress((void**)&pq2, g_pq_c2);

    lif_h1_kernel<<<2048, 256>>>((const float4*)x);
    fold_kernel<<<8, 64>>>(psF, pqF, 8, 1.f / 16384.f, gfwd, bfwd, affP + 0, affP + 512, 0);
    h2_kernel<<<8192, 256>>>();
    fold_kernel<<<16, 64>>>(psM, pqM, 32, 1.f / 8192.f, gmul, bmul, affP + 1024, affP + 2048, 1);
    mixinv_kernel<<<512, 256>>>(hw);
    fold_kernel<<<4, 64>>>(psI, pqI, 32, 1.f / 32768.f, ginv, binv, affP + 3072, affP + 3328, 0);
    conv1_kernel<<<2048, 256>>>(w1, b1);
    conv2_kernel<<<1024, 128, 48384>>>(w2, b2);
    fold_kernel<<<4, 64>>>(ps1, pq1, 128, 1.f / 32768.f, gc1, bc1, affP + 3584, affP + 3840, 0);
    fold_kernel<<<4, 64>>>(ps2, pq2, 64, 1.f / 32768.f, gc2, bc2, affP + 4096, affP + 4352, 0);
    final_kernel<<<8192, 256>>>((float4*)out);
}

// round 13
// speedup vs baseline: 1.2529x; 1.2529x over previous
#include <cuda_runtime.h>
#include <math.h>

#define RS2 0.70710678118654752440f   /* 1/sqrt(2) */

#define Tn 4
#define Bn 8
#define BCHW 2097152   /* B*C*H*W */
#define NTOT 8388608   /* T*B*C*H*W */

struct schar2 { signed char x, y; };   // explicit signedness (aarch64: plain char is unsigned!)

// ---------------- scratch (device globals) ----------------
__device__ unsigned char g_xs8[NTOT];   // spikes u8 (TB,C,32,32)
__device__ signed char g_h1c[NTOT];     // h1 codes int8 (TB,512,32,16); value = code * RS2 (gate built-in)
__device__ float g_rec[NTOT];           // pre-BN rec (TB,C,32,32)
__device__ float g_c1b[NTOT];           // pre-BN conv1 out
__device__ float g_c2b[NTOT];           // pre-BN conv2 out
__device__ float g_aff[4608];
// fwd a:0 b:512 | mul a:1024 b:2048 | inv a:3072 b:3328 | c1 a:3584 b:3840 | c2 a:4096 b:4352

__device__ float g_ps_fwd[512 * 8],   g_pq_fwd[512 * 8];
__device__ float g_ps_mul[1024 * 32], g_pq_mul[1024 * 32];
__device__ float g_ps_inv[256 * 32],  g_pq_inv[256 * 32];
__device__ float g_ps_c1[256 * 64],   g_pq_c1[256 * 64];
__device__ float g_ps_c2[256 * 64],   g_pq_c2[256 * 64];

// ---------------- LIF + Haar-W(+gate) codes + fwd-stat partials ----------------
// block = (b, c): one (b,c) 32x32 plane (256 float4), all 4 t.
__global__ void lif_h1_kernel(const float4* __restrict__ x4) {
    int blk = blockIdx.x;          // b*256 + c
    int c = blk & 255, b = blk >> 8;
    int tid = threadIdx.x;
    int i4 = blk * 256 + tid;
    int h  = tid >> 3;
    int w8 = tid & 7;
    float4 v = make_float4(0.f, 0.f, 0.f, 0.f);
    uchar4* xs4 = (uchar4*)g_xs8;
    schar2* h1c = (schar2*)g_h1c;
    float slo = 0.f, qlo = 0.f, shi = 0.f, qhi = 0.f;
#pragma unroll
    for (int t = 0; t < Tn; t++) {
        float4 xt = x4[t * (BCHW / 4) + i4];
        float4 s;
        v.x += (xt.x - v.x) * 0.5f; s.x = (v.x >= 1.0f) ? 1.f : 0.f; v.x *= (1.f - s.x);
        v.y += (xt.y - v.y) * 0.5f; s.y = (v.y >= 1.0f) ? 1.f : 0.f; v.y *= (1.f - s.y);
        v.z += (xt.z - v.z) * 0.5f; s.z = (v.z >= 1.0f) ? 1.f : 0.f; v.z *= (1.f - s.z);
        v.w += (xt.w - v.w) * 0.5f; s.w = (v.w >= 1.0f) ? 1.f : 0.f; v.w *= (1.f - s.w);
        xs4[t * (BCHW / 4) + i4] = make_uchar4((unsigned char)s.x, (unsigned char)s.y,
                                               (unsigned char)s.z, (unsigned char)s.w);
        float lo0c = s.x + s.y, hi0c = s.x - s.y;   // codes: lo in {0,1,2}, hi in {-1,0,1}
        float lo1c = s.z + s.w, hi1c = s.z - s.w;
        int n = t * Bn + b;
        int ob2 = ((n * 512 + c) * 32 + h) * 8 + w8;        // schar2 index
        schar2 plo; plo.x = (signed char)lo0c; plo.y = (signed char)lo1c;
        schar2 phi; phi.x = (signed char)hi0c; phi.y = (signed char)hi1c;
        h1c[ob2]         = plo;
        h1c[ob2 + 65536] = phi;                              // +256 channels
        float lo0 = lo0c * RS2, lo1 = lo1c * RS2, hi0 = hi0c * RS2, hi1 = hi1c * RS2;
        slo += lo0 + lo1; qlo += lo0 * lo0 + lo1 * lo1;
        shi += hi0 + hi1; qhi += hi0 * hi0 + hi1 * hi1;
    }
#pragma unroll
    for (int o = 16; o > 0; o >>= 1) {
        slo += __shfl_down_sync(0xffffffffu, slo, o);
        qlo += __shfl_down_sync(0xffffffffu, qlo, o);
        shi += __shfl_down_sync(0xffffffffu, shi, o);
        qhi += __shfl_down_sync(0xffffffffu, qhi, o);
    }
    __shared__ float R[8][4];
    if ((tid & 31) == 0) {
        int w = tid >> 5;
        R[w][0] = slo; R[w][1] = qlo; R[w][2] = shi; R[w][3] = qhi;
    }
    __syncthreads();
    if (tid < 4) {
        float a = 0.f;
#pragma unroll
        for (int w = 0; w < 8; w++) a += R[w][tid];
        if (tid == 0)      g_ps_fwd[c * 8 + b] = a;
        else if (tid == 1) g_pq_fwd[c * 8 + b] = a;
        else if (tid == 2) g_ps_fwd[(256 + c) * 8 + b] = a;
        else               g_pq_fwd[(256 + c) * 8 + b] = a;
    }
}

// ---------------- warp-per-channel fold ----------------
__global__ void foldw_kernel(const float* __restrict__ ps, const float* __restrict__ pq,
                             int P, float inv_cnt,
                             const float* __restrict__ g, const float* __restrict__ b,
                             float* __restrict__ a_out, float* __restrict__ sh_out, int gated) {
    int c = blockIdx.x * 8 + (threadIdx.x >> 5);
    int lane = threadIdx.x & 31;
    float s = 0.f, q = 0.f;
    for (int i = lane; i < P; i += 32) { s += ps[c * P + i]; q += pq[c * P + i]; }
#pragma unroll
    for (int o = 16; o > 0; o >>= 1) {
        s += __shfl_down_sync(0xffffffffu, s, o);
        q += __shfl_down_sync(0xffffffffu, q, o);
    }
    if (lane == 0) {
        float mean = s * inv_cnt, msq = q * inv_cnt;
        float var = msq - mean * mean;
        if (var < 0.f) var = 0.f;
        bool on = true;
        if (gated) {
            const float taus[4] = {0.01f, 0.02f, 0.02f, 0.05f};
            on = (msq - taus[c >> 8]) >= 0.f;
        }
        float a, sh;
        if (on) { a = g[c] / sqrtf(var + 1e-5f); sh = b[c] - mean * a; }
        else    { a = 0.f; sh = b[c]; }
        a_out[c] = a; sh_out[c] = sh;
    }
}

// ---------------- combined tail fold (inv + c1 + c2), all cnt=32768 ----------------
__global__ void fold3_kernel(const float* __restrict__ gi, const float* __restrict__ bi,
                             const float* __restrict__ g1, const float* __restrict__ b1,
                             const float* __restrict__ g2, const float* __restrict__ b2) {
    int c = blockIdx.x * 8 + (threadIdx.x >> 5);   // 0..767
    int lane = threadIdx.x & 31;
    const float *ps, *pq, *g, *b;
    int P, cc, ao, so;
    if (c < 256)      { ps = g_ps_inv; pq = g_pq_inv; P = 32; cc = c;       g = gi; b = bi; ao = 3072; so = 3328; }
    else if (c < 512) { ps = g_ps_c1;  pq = g_pq_c1;  P = 64; cc = c - 256; g = g1; b = b1; ao = 3584; so = 3840; }
    else              { ps = g_ps_c2;  pq = g_pq_c2;  P = 64; cc = c - 512; g = g2; b = b2; ao = 4096; so = 4352; }
    float s = 0.f, q = 0.f;
    for (int i = lane; i < P; i += 32) { s += ps[cc * P + i]; q += pq[cc * P + i]; }
#pragma unroll
    for (int o = 16; o > 0; o >>= 1) {
        s += __shfl_down_sync(0xffffffffu, s, o);
        q += __shfl_down_sync(0xffffffffu, q, o);
    }
    if (lane == 0) {
        float inv_cnt = 1.f / 32768.f;
        float mean = s * inv_cnt, msq = q * inv_cnt;
        float var = msq - mean * mean;
        if (var < 0.f) var = 0.f;
        float a = g[cc] / sqrtf(var + 1e-5f);
        float sh = b[cc] - mean * a;
        g_aff[ao + cc] = a; g_aff[so + cc] = sh;
    }
}

// ---------------- h2 stats only (reads h1 codes; no h2 materialization) ----------------
__global__ void stats_h2_kernel() {
    int blk = blockIdx.x;       // n*256 + c
    int c = blk & 255, n = blk >> 8;
    int tid = threadIdx.x;      // h2*16 + w2
    int h2 = tid >> 4, w2 = tid & 15;
    float aL = g_aff[c],       bL = g_aff[512 + c];
    float aH = g_aff[256 + c], bH = g_aff[768 + c];
    const signed char* pL = g_h1c + ((n * 512 + c) * 32 + 2 * h2) * 16 + w2;
    const signed char* pH = pL + 131072;
    float L0 = (float)pL[0]  * RS2 * aL + bL;
    float L1 = (float)pL[16] * RS2 * aL + bL;
    float G0 = (float)pH[0]  * RS2 * aH + bH;
    float G1 = (float)pH[16] * RS2 * aH + bH;
    float LL = (L0 + L1) * RS2, HL = (L0 - L1) * RS2;
    float LH = (G0 + G1) * RS2, HH = (G0 - G1) * RS2;
    LL = (fabsf(LL) >= 0.5f) ? LL : 0.f;
    HL = (fabsf(HL) >= 0.5f) ? HL : 0.f;
    LH = (fabsf(LH) >= 0.5f) ? LH : 0.f;
    HH = (fabsf(HH) >= 0.5f) ? HH : 0.f;
    float sv[8] = {LL, LL * LL, HL, HL * HL, LH, LH * LH, HH, HH * HH};
#pragma unroll
    for (int j = 0; j < 8; j++)
#pragma unroll
        for (int o = 16; o > 0; o >>= 1)
            sv[j] += __shfl_down_sync(0xffffffffu, sv[j], o);
    __shared__ float R[8][8];
    if ((tid & 31) == 0) {
        int w = tid >> 5;
#pragma unroll
        for (int j = 0; j < 8; j++) R[w][j] = sv[j];
    }
    __syncthreads();
    if (tid < 8) {
        float a = 0.f;
#pragma unroll
        for (int w = 0; w < 8; w++) a += R[w][tid];
        int band = tid >> 1;
        int idx = (band * 256 + c) * 32 + n;
        if ((tid & 1) == 0) g_ps_mul[idx] = a;
        else                g_pq_mul[idx] = a;
    }
}

// ---------------- recompute-h2 + gate+BN(mul) + 16x16 mix + inverse Haar + inv partials ----------------
__global__ void __launch_bounds__(256) mixinv_kernel(const float* __restrict__ hw) {
    int n = blockIdx.x >> 4, cg = blockIdx.x & 15;
    int tid = threadIdx.x;     // h2*16 + w2
    __shared__ __align__(16) float Wsh[4][256];
    __shared__ float Am[4][16], Bm[4][16];
    __shared__ float aLs[16], bLs[16], aHs[16], bHs[16];
#pragma unroll
    for (int band = 0; band < 4; band++) {
        int nb = band * 4 + (cg >> 2);
        Wsh[band][tid] = hw[nb * 256 + tid];
    }
    if (tid < 64) {
        int band = tid >> 4, k = tid & 15;
        int ch = band * 256 + cg * 16 + k;
        Am[band][k] = g_aff[1024 + ch];
        Bm[band][k] = g_aff[2048 + ch];
    }
    if (tid < 16) {
        int ch = cg * 16 + tid;
        aLs[tid] = g_aff[ch];       bLs[tid] = g_aff[512 + ch];
        aHs[tid] = g_aff[256 + ch]; bHs[tid] = g_aff[768 + ch];
    }
    __syncthreads();
    int h2i = tid >> 4, w2 = tid & 15;
    float out[4][16];
#pragma unroll
    for (int band = 0; band < 4; band++)
#pragma unroll
        for (int k = 0; k < 16; k++) out[band][k] = 0.f;
    const signed char* base = g_h1c + ((n * 512 + cg * 16) * 32 + 2 * h2i) * 16 + w2;
#pragma unroll
    for (int d = 0; d < 16; d++) {
        const signed char* pL = base + d * 512;
        const signed char* pH = pL + 131072;
        float L0 = (float)pL[0]  * RS2 * aLs[d] + bLs[d];
        float L1 = (float)pL[16] * RS2 * aLs[d] + bLs[d];
        float G0 = (float)pH[0]  * RS2 * aHs[d] + bHs[d];
        float G1 = (float)pH[16] * RS2 * aHs[d] + bHs[d];
        float LL = (L0 + L1) * RS2, HL = (L0 - L1) * RS2;
        float LH = (G0 + G1) * RS2, HH = (G0 - G1) * RS2;
        LL = (fabsf(LL) >= 0.5f) ? LL : 0.f;
        HL = (fabsf(HL) >= 0.5f) ? HL : 0.f;
        LH = (fabsf(LH) >= 0.5f) ? LH : 0.f;
        HH = (fabsf(HH) >= 0.5f) ? HH : 0.f;
        float xb0 = LL * Am[0][d] + Bm[0][d];
        float xb1 = HL * Am[1][d] + Bm[1][d];
        float xb2 = LH * Am[2][d] + Bm[2][d];
        float xb3 = HH * Am[3][d] + Bm[3][d];
        float xbv[4] = {xb0, xb1, xb2, xb3};
#pragma unroll
        for (int band = 0; band < 4; band++) {
            const float4* wr = (const float4*)&Wsh[band][d * 16];
#pragma unroll
            for (int k4 = 0; k4 < 4; k4++) {
                float4 wv = wr[k4];
                out[band][k4 * 4 + 0] = fmaf(xbv[band], wv.x, out[band][k4 * 4 + 0]);
                out[band][k4 * 4 + 1] = fmaf(xbv[band], wv.y, out[band][k4 * 4 + 1]);
                out[band][k4 * 4 + 2] = fmaf(xbv[band], wv.z, out[band][k4 * 4 + 2]);
                out[band][k4 * 4 + 3] = fmaf(xbv[band], wv.w, out[band][k4 * 4 + 3]);
            }
        }
    }
    float sk[16], qk[16];
    float2* rec2 = (float2*)g_rec;
#pragma unroll
    for (int k = 0; k < 16; k++) {
        float A = out[0][k], B = out[1][k], C = out[2][k], D = out[3][k];
        float Lr0 = (A + B) * RS2, Lr1 = (A - B) * RS2;
        float Hr0 = (C + D) * RS2, Hr1 = (C - D) * RS2;
        int c = cg * 16 + k;
        int ob2 = (((n * 256 + c) * 32 + 2 * h2i) * 32 + 2 * w2) >> 1;
        rec2[ob2]      = make_float2((Lr0 + Hr0) * RS2, (Lr0 - Hr0) * RS2);
        rec2[ob2 + 16] = make_float2((Lr1 + Hr1) * RS2, (Lr1 - Hr1) * RS2);
        sk[k] = 2.0f * A;                       // exact sum of 4 rec values
        qk[k] = A * A + B * B + C * C + D * D;  // exact sumsq (orthogonality)
    }
#pragma unroll
    for (int k = 0; k < 16; k++)
#pragma unroll
        for (int o = 16; o > 0; o >>= 1) {
            sk[k] += __shfl_down_sync(0xffffffffu, sk[k], o);
            qk[k] += __shfl_down_sync(0xffffffffu, qk[k], o);
        }
    __shared__ float R[16][2][8];
    if ((tid & 31) == 0) {
        int w = tid >> 5;
#pragma unroll
        for (int k = 0; k < 16; k++) { R[k][0][w] = sk[k]; R[k][1][w] = qk[k]; }
    }
    __syncthreads();
    if (tid < 32) {
        int k = tid >> 1, j = tid & 1;
        float a = 0.f;
#pragma unroll
        for (int w = 0; w < 8; w++) a += R[k][j][w];
        int idx = (cg * 16 + k) * 32 + n;
        if (j == 0) g_ps_inv[idx] = a;
        else        g_pq_inv[idx] = a;
    }
}

// ---------------- fused 3x3 + 1x1 conv over 16-channel blocks + partials ----------------
// u8 spike tile in smem (spikes are {0,1}); all-static smem ~20.7 KB, no dynamic.
__global__ void __launch_bounds__(128) conv_kernel(const float* __restrict__ w2,
                                                   const float* __restrict__ b2,
                                                   const float* __restrict__ w1,
                                                   const float* __restrict__ b1) {
    int blk = blockIdx.x;      // 0..1023
    int ns = blk >> 1;
    int h0 = (blk & 1) * 16;
    __shared__ unsigned char tile8[16 * 612];   // 16ch x 18row x 34col, u8
    __shared__ float wsh[2304];
    __shared__ float w1sh[256];
    __shared__ float bsh2[16], bsh1[16];
    __shared__ float R[16][2][4];
    int tid = threadIdx.x;
    for (int i = tid; i < 2304; i += 128) wsh[i] = w2[i];
    for (int i = tid; i < 256; i += 128) w1sh[i] = w1[i];
    if (tid < 16) { bsh2[tid] = b2[tid]; bsh1[tid] = b1[tid]; }
    const unsigned char* xin = g_xs8 + ns * 16384;
    for (int i = tid; i < 9792; i += 128) {
        int d = i / 612;
        int rem = i - d * 612;
        int row = rem / 34;
        int colp = rem - row * 34;
        int gr = h0 + row - 1, gc = colp - 1;
        unsigned char v = 0;
        if ((unsigned)gr < 32u && (unsigned)gc < 32u) v = xin[d * 1024 + gr * 32 + gc];
        tile8[i] = v;
    }
    __syncthreads();
    int col = tid & 31;
    int r0 = (tid >> 5) * 4;
    float acc[16][4];
#pragma unroll
    for (int k = 0; k < 16; k++) {
        float bv = bsh2[k];
#pragma unroll
        for (int rr = 0; rr < 4; rr++) acc[k][rr] = bv;
    }
    for (int d = 0; d < 16; d++) {
        float xr[6][3];
#pragma unroll
        for (int rr = 0; rr < 6; rr++)
#pragma unroll
            for (int cc = 0; cc < 3; cc++)
                xr[rr][cc] = (float)tile8[d * 612 + (r0 + rr) * 34 + col + cc];
#pragma unroll
        for (int k = 0; k < 16; k++) {
            const float* wp = wsh + (k * 16 + d) * 9;
            float w0 = wp[0], w1v = wp[1], w2v = wp[2];
            float w3 = wp[3], w4  = wp[4], w5  = wp[5];
            float w6 = wp[6], w7  = wp[7], w8  = wp[8];
#pragma unroll
            for (int rr = 0; rr < 4; rr++) {
                float a = acc[k][rr];
                a = fmaf(w0, xr[rr][0],     a);
                a = fmaf(w1v, xr[rr][1],    a);
                a = fmaf(w2v, xr[rr][2],    a);
                a = fmaf(w3, xr[rr + 1][0], a);
                a = fmaf(w4, xr[rr + 1][1], a);
                a = fmaf(w5, xr[rr + 1][2], a);
                a = fmaf(w6, xr[rr + 2][0], a);
                a = fmaf(w7, xr[rr + 2][1], a);
                a = fmaf(w8, xr[rr + 2][2], a);
                acc[k][rr] = a;
            }
        }
    }
    int nb = ns & 15, nn = ns >> 4;
    // ---- conv2 store + stats ----
    {
        float* op = g_c2b + ns * 16384;
        float sk[16], qk[16];
#pragma unroll
        for (int k = 0; k < 16; k++) {
            float s = 0.f, q = 0.f;
#pragma unroll
            for (int rr = 0; rr < 4; rr++) {
                float a = acc[k][rr];
                op[k * 1024 + (h0 + r0 + rr) * 32 + col] = a;
                s += a; q += a * a;
            }
            sk[k] = s; qk[k] = q;
        }
#pragma unroll
        for (int k = 0; k < 16; k++)
#pragma unroll
            for (int o = 16; o > 0; o >>= 1) {
                sk[k] += __shfl_down_sync(0xffffffffu, sk[k], o);
                qk[k] += __shfl_down_sync(0xffffffffu, qk[k], o);
            }
        if ((tid & 31) == 0) {
            int w = tid >> 5;
#pragma unroll
            for (int k = 0; k < 16; k++) { R[k][0][w] = sk[k]; R[k][1][w] = qk[k]; }
        }
        __syncthreads();
        if (tid < 32) {
            int k = tid >> 1, j = tid & 1;
            float a = 0.f;
#pragma unroll
            for (int w = 0; w < 4; w++) a += R[k][j][w];
            int idx = (nb * 16 + k) * 64 + nn * 2 + (blk & 1);
            if (j == 0) g_ps_c2[idx] = a;
            else        g_pq_c2[idx] = a;
        }
        __syncthreads();
    }
    // ---- conv1 (reuse tile + acc registers) ----
#pragma unroll
    for (int k = 0; k < 16; k++) {
        float bv = bsh1[k];
#pragma unroll
        for (int rr = 0; rr < 4; rr++) acc[k][rr] = bv;
    }
    for (int d = 0; d < 16; d++) {
        float ce[4];
#pragma unroll
        for (int rr = 0; rr < 4; rr++) ce[rr] = (float)tile8[d * 612 + (r0 + rr + 1) * 34 + col + 1];
#pragma unroll
        for (int k = 0; k < 16; k++) {
            float wv = w1sh[k * 16 + d];
#pragma unroll
            for (int rr = 0; rr < 4; rr++) acc[k][rr] = fmaf(wv, ce[rr], acc[k][rr]);
        }
    }
    {
        float* op = g_c1b + ns * 16384;
        float sk[16], qk[16];
#pragma unroll
        for (int k = 0; k < 16; k++) {
            float s = 0.f, q = 0.f;
#pragma unroll
            for (int rr = 0; rr < 4; rr++) {
                float a = acc[k][rr];
                op[k * 1024 + (h0 + r0 + rr) * 32 + col] = a;
                s += a; q += a * a;
            }
            sk[k] = s; qk[k] = q;
        }
#pragma unroll
        for (int k = 0; k < 16; k++)
#pragma unroll
            for (int o = 16; o > 0; o >>= 1) {
                sk[k] += __shfl_down_sync(0xffffffffu, sk[k], o);
                qk[k] += __shfl_down_sync(0xffffffffu, qk[k], o);
            }
        if ((tid & 31) == 0) {
            int w = tid >> 5;
#pragma unroll
            for (int k = 0; k < 16; k++) { R[k][0][w] = sk[k]; R[k][1][w] = qk[k]; }
        }
        __syncthreads();
        if (tid < 32) {
            int k = tid >> 1, j = tid & 1;
            float a = 0.f;
#pragma unroll
            for (int w = 0; w < 4; w++) a += R[k][j][w];
            int idx = (nb * 16 + k) * 64 + nn * 2 + (blk & 1);
            if (j == 0) g_ps_c1[idx] = a;
            else        g_pq_c1[idx] = a;
        }
    }
}

// ---------------- final: BN-apply x3 + sum (float4) ----------------
__global__ void final_kernel(float4* __restrict__ out) {
    int i4 = blockIdx.x * 256 + threadIdx.x;
    int c = (i4 >> 8) & 255;
    float ar = g_aff[3072 + c], br = g_aff[3328 + c];
    float a1 = g_aff[3584 + c], b1 = g_aff[3840 + c];
    float a2 = g_aff[4096 + c], b2 = g_aff[4352 + c];
    float4 r = ((const float4*)g_rec)[i4];
    float4 u = ((const float4*)g_c1b)[i4];
    float4 v = ((const float4*)g_c2b)[i4];
    float4 o;
    o.x = r.x * ar + br + u.x * a1 + b1 + v.x * a2 + b2;
    o.y = r.y * ar + br + u.y * a1 + b1 + v.y * a2 + b2;
    o.z = r.z * ar + br + u.z * a1 + b1 + v.z * a2 + b2;
    o.w = r.w * ar + br + u.w * a1 + b1 + v.w * a2 + b2;
    out[i4] = o;
}

// ---------------- host ----------------
extern "C" void kernel_launch(void* const* d_in, const int* in_sizes, int n_in,
                              void* d_out, int out_size) {
    const float* x    = (const float*)d_in[0];
    const float* hw   = (const float*)d_in[1];
    const float* w1   = (const float*)d_in[2];
    const float* b1   = (const float*)d_in[3];
    const float* w2   = (const float*)d_in[4];
    const float* b2   = (const float*)d_in[5];
    const float* gfwd = (const float*)d_in[6];
    const float* bfwd = (const float*)d_in[7];
    const float* gmul = (const float*)d_in[8];
    const float* bmul = (const float*)d_in[9];
    const float* ginv = (const float*)d_in[10];
    const float* binv = (const float*)d_in[11];
    const float* gc1  = (const float*)d_in[12];
    const float* bc1  = (const float*)d_in[13];
    const float* gc2  = (const float*)d_in[14];
    const float* bc2  = (const float*)d_in[15];
    float* out = (float*)d_out;

    float *affP, *psF, *pqF, *psM, *pqM;
    cudaGetSymbolAddress((void**)&affP, g_aff);
    cudaGetSymbolAddress((void**)&psF, g_ps_fwd);
    cudaGetSymbolAddress((void**)&pqF, g_pq_fwd);
    cudaGetSymbolAddress((void**)&psM, g_ps_mul);
    cudaGetSymbolAddress((void**)&pqM, g_pq_mul);

    lif_h1_kernel<<<2048, 256>>>((const float4*)x);
    foldw_kernel<<<64, 256>>>(psF, pqF, 8, 1.f / 16384.f, gfwd, bfwd, affP + 0, affP + 512, 0);
    stats_h2_kernel<<<8192, 256>>>();
    foldw_kernel<<<128, 256>>>(psM, pqM, 32, 1.f / 8192.f, gmul, bmul, affP + 1024, affP + 2048, 1);
    mixinv_kernel<<<512, 256>>>(hw);
    conv_kernel<<<1024, 128>>>(w2, b2, w1, b1);
    fold3_kernel<<<96, 256>>>(ginv, binv, gc1, bc1, gc2, bc2);
    final_kernel<<<8192, 256>>>((float4*)out);
}

// round 14
// speedup vs baseline: 1.3081x; 1.0440x over previous
#include <cuda_runtime.h>
#include <math.h>

#define RS2 0.70710678118654752440f   /* 1/sqrt(2) */

#define Tn 4
#define Bn 8
#define BCHW 2097152   /* B*C*H*W */
#define NTOT 8388608   /* T*B*C*H*W */

struct schar2 { signed char x, y; };   // explicit signedness (aarch64: plain char is unsigned!)

// ---------------- scratch (device globals) ----------------
__device__ unsigned char g_xs8[NTOT];   // spikes u8 (TB,C,32,32)
__device__ signed char g_h1c[NTOT];     // h1 codes int8 (TB,512,32,16); value = code * RS2 (gate built-in)
__device__ float g_rec[NTOT];           // pre-BN rec (TB,C,32,32)
__device__ float g_c1b[NTOT];           // pre-BN conv1 out
__device__ float g_c2b[NTOT];           // pre-BN conv2 out

__device__ float g_ps_fwd[512 * 8],   g_pq_fwd[512 * 8];
__device__ float g_ps_mul[1024 * 4],  g_pq_mul[1024 * 4];
__device__ float g_ps_inv[256 * 32],  g_pq_inv[256 * 32];
__device__ float g_ps_c1[256 * 64],   g_pq_c1[256 * 64];
__device__ float g_ps_c2[256 * 64],   g_pq_c2[256 * 64];

// ---------------- LIF + Haar-W(+gate) codes + fwd-stat partials ----------------
// block = (b, c): one (b,c) 32x32 plane (256 float4), all 4 t.
__global__ void lif_h1_kernel(const float4* __restrict__ x4) {
    int blk = blockIdx.x;          // b*256 + c
    int c = blk & 255, b = blk >> 8;
    int tid = threadIdx.x;
    int i4 = blk * 256 + tid;
    int h  = tid >> 3;
    int w8 = tid & 7;
    float4 v = make_float4(0.f, 0.f, 0.f, 0.f);
    uchar4* xs4 = (uchar4*)g_xs8;
    schar2* h1c = (schar2*)g_h1c;
    float slo = 0.f, qlo = 0.f, shi = 0.f, qhi = 0.f;
#pragma unroll
    for (int t = 0; t < Tn; t++) {
        float4 xt = x4[t * (BCHW / 4) + i4];
        float4 s;
        v.x += (xt.x - v.x) * 0.5f; s.x = (v.x >= 1.0f) ? 1.f : 0.f; v.x *= (1.f - s.x);
        v.y += (xt.y - v.y) * 0.5f; s.y = (v.y >= 1.0f) ? 1.f : 0.f; v.y *= (1.f - s.y);
        v.z += (xt.z - v.z) * 0.5f; s.z = (v.z >= 1.0f) ? 1.f : 0.f; v.z *= (1.f - s.z);
        v.w += (xt.w - v.w) * 0.5f; s.w = (v.w >= 1.0f) ? 1.f : 0.f; v.w *= (1.f - s.w);
        xs4[t * (BCHW / 4) + i4] = make_uchar4((unsigned char)s.x, (unsigned char)s.y,
                                               (unsigned char)s.z, (unsigned char)s.w);
        float lo0c = s.x + s.y, hi0c = s.x - s.y;   // codes: lo in {0,1,2}, hi in {-1,0,1}
        float lo1c = s.z + s.w, hi1c = s.z - s.w;
        int n = t * Bn + b;
        int ob2 = ((n * 512 + c) * 32 + h) * 8 + w8;        // schar2 index
        schar2 plo; plo.x = (signed char)lo0c; plo.y = (signed char)lo1c;
        schar2 phi; phi.x = (signed char)hi0c; phi.y = (signed char)hi1c;
        h1c[ob2]         = plo;
        h1c[ob2 + 65536] = phi;                              // +256 channels
        float lo0 = lo0c * RS2, lo1 = lo1c * RS2, hi0 = hi0c * RS2, hi1 = hi1c * RS2;
        slo += lo0 + lo1; qlo += lo0 * lo0 + lo1 * lo1;
        shi += hi0 + hi1; qhi += hi0 * hi0 + hi1 * hi1;
    }
#pragma unroll
    for (int o = 16; o > 0; o >>= 1) {
        slo += __shfl_down_sync(0xffffffffu, slo, o);
        qlo += __shfl_down_sync(0xffffffffu, qlo, o);
        shi += __shfl_down_sync(0xffffffffu, shi, o);
        qhi += __shfl_down_sync(0xffffffffu, qhi, o);
    }
    __shared__ float R[8][4];
    if ((tid & 31) == 0) {
        int w = tid >> 5;
        R[w][0] = slo; R[w][1] = qlo; R[w][2] = shi; R[w][3] = qhi;
    }
    __syncthreads();
    if (tid < 4) {
        float a = 0.f;
#pragma unroll
        for (int w = 0; w < 8; w++) a += R[w][tid];
        if (tid == 0)      g_ps_fwd[c * 8 + b] = a;
        else if (tid == 1) g_pq_fwd[c * 8 + b] = a;
        else if (tid == 2) g_ps_fwd[(256 + c) * 8 + b] = a;
        else               g_pq_fwd[(256 + c) * 8 + b] = a;
    }
}

// ---------------- h2 stats: fwd-affine inline + partial mul sums ----------------
// block = (c, quarter): 8 samples, one channel. grid 1024.
__global__ void __launch_bounds__(256) stats_h2_kernel(const float* __restrict__ gfwd,
                                                       const float* __restrict__ bfwd) {
    int c = blockIdx.x >> 2, qr = blockIdx.x & 3;
    int tid = threadIdx.x;
    __shared__ float sAff[4];   // aL,bL,aH,bH
    // warp 0: fold fwd partials for channels c (L) and 256+c (H)
    if (tid < 32) {
        int grp = tid >> 3;     // 0:psL 1:pqL 2:psH 3:pqH
        int b = tid & 7;
        int ch = (grp < 2) ? c : 256 + c;
        const float* src = ((grp & 1) == 0) ? g_ps_fwd : g_pq_fwd;
        float v = src[ch * 8 + b];
        v += __shfl_down_sync(0xffffffffu, v, 4);
        v += __shfl_down_sync(0xffffffffu, v, 2);
        v += __shfl_down_sync(0xffffffffu, v, 1);
        float sL = __shfl_sync(0xffffffffu, v, 0);
        float qL = __shfl_sync(0xffffffffu, v, 8);
        float sH = __shfl_sync(0xffffffffu, v, 16);
        float qH = __shfl_sync(0xffffffffu, v, 24);
        if (tid == 0) {
            float inv = 1.f / 16384.f;
            float mean = sL * inv, msq = qL * inv;
            float var = msq - mean * mean; if (var < 0.f) var = 0.f;
            float a = gfwd[c] / sqrtf(var + 1e-5f);
            sAff[0] = a; sAff[1] = bfwd[c] - mean * a;
            mean = sH * inv; msq = qH * inv;
            var = msq - mean * mean; if (var < 0.f) var = 0.f;
            a = gfwd[256 + c] / sqrtf(var + 1e-5f);
            sAff[2] = a; sAff[3] = bfwd[256 + c] - mean * a;
        }
    }
    __syncthreads();
    float aL = sAff[0], bL = sAff[1], aH = sAff[2], bH = sAff[3];
    int h2 = tid >> 4, w2 = tid & 15;
    float sv[8] = {0.f, 0.f, 0.f, 0.f, 0.f, 0.f, 0.f, 0.f};
#pragma unroll
    for (int ni = 0; ni < 8; ni++) {
        int n = qr * 8 + ni;
        const signed char* pL = g_h1c + ((n * 512 + c) * 32 + 2 * h2) * 16 + w2;
        const signed char* pH = pL + 131072;
        float L0 = (float)pL[0]  * RS2 * aL + bL;
        float L1 = (float)pL[16] * RS2 * aL + bL;
        float G0 = (float)pH[0]  * RS2 * aH + bH;
        float G1 = (float)pH[16] * RS2 * aH + bH;
        float LL = (L0 + L1) * RS2, HL = (L0 - L1) * RS2;
        float LH = (G0 + G1) * RS2, HH = (G0 - G1) * RS2;
        LL = (fabsf(LL) >= 0.5f) ? LL : 0.f;
        HL = (fabsf(HL) >= 0.5f) ? HL : 0.f;
        LH = (fabsf(LH) >= 0.5f) ? LH : 0.f;
        HH = (fabsf(HH) >= 0.5f) ? HH : 0.f;
        sv[0] += LL; sv[1] += LL * LL;
        sv[2] += HL; sv[3] += HL * HL;
        sv[4] += LH; sv[5] += LH * LH;
        sv[6] += HH; sv[7] += HH * HH;
    }
#pragma unroll
    for (int j = 0; j < 8; j++)
#pragma unroll
        for (int o = 16; o > 0; o >>= 1)
            sv[j] += __shfl_down_sync(0xffffffffu, sv[j], o);
    __shared__ float R[8][8];
    if ((tid & 31) == 0) {
        int w = tid >> 5;
#pragma unroll
        for (int j = 0; j < 8; j++) R[w][j] = sv[j];
    }
    __syncthreads();
    if (tid < 8) {
        float a = 0.f;
#pragma unroll
        for (int w = 0; w < 8; w++) a += R[w][tid];
        int band = tid >> 1;
        int idx = (band * 256 + c) * 4 + qr;
        if ((tid & 1) == 0) g_ps_mul[idx] = a;
        else                g_pq_mul[idx] = a;
    }
}

// ---------------- recompute-h2 + inline affines + 16x16 mix + inverse Haar + inv partials ----------------
__global__ void __launch_bounds__(256) mixinv_kernel(const float* __restrict__ hw,
                                                     const float* __restrict__ gfwd,
                                                     const float* __restrict__ bfwd,
                                                     const float* __restrict__ gmul,
                                                     const float* __restrict__ bmul) {
    int n = blockIdx.x >> 4, cg = blockIdx.x & 15;
    int tid = threadIdx.x;     // h2*16 + w2
    __shared__ __align__(16) float Wsh[4][256];
    __shared__ float Am[4][16], Bm[4][16];
    __shared__ float aLs[16], bLs[16], aHs[16], bHs[16];
#pragma unroll
    for (int band = 0; band < 4; band++) {
        int nb = band * 4 + (cg >> 2);
        Wsh[band][tid] = hw[nb * 256 + tid];
    }
    // mul affine inline (4 partials per channel + gating)
    if (tid < 64) {
        int band = tid >> 4, k = tid & 15;
        int ch = band * 256 + cg * 16 + k;
        float s = 0.f, q = 0.f;
#pragma unroll
        for (int i = 0; i < 4; i++) { s += g_ps_mul[ch * 4 + i]; q += g_pq_mul[ch * 4 + i]; }
        float inv = 1.f / 8192.f;
        float mean = s * inv, msq = q * inv;
        float var = msq - mean * mean; if (var < 0.f) var = 0.f;
        const float taus[4] = {0.01f, 0.02f, 0.02f, 0.05f};
        bool on = (msq - taus[band]) >= 0.f;
        float a, sh;
        if (on) { a = gmul[ch] / sqrtf(var + 1e-5f); sh = bmul[ch] - mean * a; }
        else    { a = 0.f; sh = bmul[ch]; }
        Am[band][k] = a; Bm[band][k] = sh;
    }
    // fwd affine inline: 32 channels (16 L + 16 H), 8 partials each = 256 threads
    {
        int chi = tid >> 3;      // 0..31
        int b = tid & 7;
        int ch = (chi < 16) ? (cg * 16 + chi) : (256 + cg * 16 + (chi - 16));
        float s = g_ps_fwd[ch * 8 + b];
        float q = g_pq_fwd[ch * 8 + b];
        s += __shfl_down_sync(0xffffffffu, s, 4);
        q += __shfl_down_sync(0xffffffffu, q, 4);
        s += __shfl_down_sync(0xffffffffu, s, 2);
        q += __shfl_down_sync(0xffffffffu, q, 2);
        s += __shfl_down_sync(0xffffffffu, s, 1);
        q += __shfl_down_sync(0xffffffffu, q, 1);
        if (b == 0) {
            float inv = 1.f / 16384.f;
            float mean = s * inv, msq = q * inv;
            float var = msq - mean * mean; if (var < 0.f) var = 0.f;
            float gch = (chi < 16) ? gfwd[ch] : gfwd[ch];
            float a = gch / sqrtf(var + 1e-5f);
            float sh = bfwd[ch] - mean * a;
            if (chi < 16) { aLs[chi] = a; bLs[chi] = sh; }
            else          { aHs[chi - 16] = a; bHs[chi - 16] = sh; }
        }
    }
    __syncthreads();
    int h2i = tid >> 4, w2 = tid & 15;
    float out[4][16];
#pragma unroll
    for (int band = 0; band < 4; band++)
#pragma unroll
        for (int k = 0; k < 16; k++) out[band][k] = 0.f;
    const signed char* base = g_h1c + ((n * 512 + cg * 16) * 32 + 2 * h2i) * 16 + w2;
#pragma unroll
    for (int d = 0; d < 16; d++) {
        const signed char* pL = base + d * 512;
        const signed char* pH = pL + 131072;
        float L0 = (float)pL[0]  * RS2 * aLs[d] + bLs[d];
        float L1 = (float)pL[16] * RS2 * aLs[d] + bLs[d];
        float G0 = (float)pH[0]  * RS2 * aHs[d] + bHs[d];
        float G1 = (float)pH[16] * RS2 * aHs[d] + bHs[d];
        float LL = (L0 + L1) * RS2, HL = (L0 - L1) * RS2;
        float LH = (G0 + G1) * RS2, HH = (G0 - G1) * RS2;
        LL = (fabsf(LL) >= 0.5f) ? LL : 0.f;
        HL = (fabsf(HL) >= 0.5f) ? HL : 0.f;
        LH = (fabsf(LH) >= 0.5f) ? LH : 0.f;
        HH = (fabsf(HH) >= 0.5f) ? HH : 0.f;
        float xbv[4];
        xbv[0] = LL * Am[0][d] + Bm[0][d];
        xbv[1] = HL * Am[1][d] + Bm[1][d];
        xbv[2] = LH * Am[2][d] + Bm[2][d];
        xbv[3] = HH * Am[3][d] + Bm[3][d];
#pragma unroll
        for (int band = 0; band < 4; band++) {
            const float4* wr = (const float4*)&Wsh[band][d * 16];
#pragma unroll
            for (int k4 = 0; k4 < 4; k4++) {
                float4 wv = wr[k4];
                out[band][k4 * 4 + 0] = fmaf(xbv[band], wv.x, out[band][k4 * 4 + 0]);
                out[band][k4 * 4 + 1] = fmaf(xbv[band], wv.y, out[band][k4 * 4 + 1]);
                out[band][k4 * 4 + 2] = fmaf(xbv[band], wv.z, out[band][k4 * 4 + 2]);
                out[band][k4 * 4 + 3] = fmaf(xbv[band], wv.w, out[band][k4 * 4 + 3]);
            }
        }
    }
    float sk[16], qk[16];
    float2* rec2 = (float2*)g_rec;
#pragma unroll
    for (int k = 0; k < 16; k++) {
        float A = out[0][k], B = out[1][k], C = out[2][k], D = out[3][k];
        float Lr0 = (A + B) * RS2, Lr1 = (A - B) * RS2;
        float Hr0 = (C + D) * RS2, Hr1 = (C - D) * RS2;
        int c = cg * 16 + k;
        int ob2 = (((n * 256 + c) * 32 + 2 * h2i) * 32 + 2 * w2) >> 1;
        rec2[ob2]      = make_float2((Lr0 + Hr0) * RS2, (Lr0 - Hr0) * RS2);
        rec2[ob2 + 16] = make_float2((Lr1 + Hr1) * RS2, (Lr1 - Hr1) * RS2);
        sk[k] = 2.0f * A;                       // exact sum of 4 rec values
        qk[k] = A * A + B * B + C * C + D * D;  // exact sumsq (orthogonality)
    }
#pragma unroll
    for (int k = 0; k < 16; k++)
#pragma unroll
        for (int o = 16; o > 0; o >>= 1) {
            sk[k] += __shfl_down_sync(0xffffffffu, sk[k], o);
            qk[k] += __shfl_down_sync(0xffffffffu, qk[k], o);
        }
    __shared__ float R[16][2][8];
    if ((tid & 31) == 0) {
        int w = tid >> 5;
#pragma unroll
        for (int k = 0; k < 16; k++) { R[k][0][w] = sk[k]; R[k][1][w] = qk[k]; }
    }
    __syncthreads();
    if (tid < 32) {
        int k = tid >> 1, j = tid & 1;
        float a = 0.f;
#pragma unroll
        for (int w = 0; w < 8; w++) a += R[k][j][w];
        int idx = (cg * 16 + k) * 32 + n;
        if (j == 0) g_ps_inv[idx] = a;
        else        g_pq_inv[idx] = a;
    }
}

// ---------------- fused 3x3 + 1x1 conv over 16-channel blocks + partials ----------------
__global__ void __launch_bounds__(128) conv_kernel(const float* __restrict__ w2,
                                                   const float* __restrict__ b2,
                                                   const float* __restrict__ w1,
                                                   const float* __restrict__ b1) {
    int blk = blockIdx.x;      // 0..1023
    int ns = blk >> 1;
    int h0 = (blk & 1) * 16;
    __shared__ unsigned char tile8[16 * 612];   // 16ch x 18row x 34col, u8
    __shared__ float wsh[2304];
    __shared__ float w1sh[256];
    __shared__ float bsh2[16], bsh1[16];
    __shared__ float R[16][2][4];
    int tid = threadIdx.x;
    for (int i = tid; i < 2304; i += 128) wsh[i] = w2[i];
    for (int i = tid; i < 256; i += 128) w1sh[i] = w1[i];
    if (tid < 16) { bsh2[tid] = b2[tid]; bsh1[tid] = b1[tid]; }
    const unsigned char* xin = g_xs8 + ns * 16384;
    for (int i = tid; i < 9792; i += 128) {
        int d = i / 612;
        int rem = i - d * 612;
        int row = rem / 34;
        int colp = rem - row * 34;
        int gr = h0 + row - 1, gc = colp - 1;
        unsigned char v = 0;
        if ((unsigned)gr < 32u && (unsigned)gc < 32u) v = xin[d * 1024 + gr * 32 + gc];
        tile8[i] = v;
    }
    __syncthreads();
    int col = tid & 31;
    int r0 = (tid >> 5) * 4;
    float acc[16][4];
#pragma unroll
    for (int k = 0; k < 16; k++) {
        float bv = bsh2[k];
#pragma unroll
        for (int rr = 0; rr < 4; rr++) acc[k][rr] = bv;
    }
    for (int d = 0; d < 16; d++) {
        float xr[6][3];
#pragma unroll
        for (int rr = 0; rr < 6; rr++)
#pragma unroll
            for (int cc = 0; cc < 3; cc++)
                xr[rr][cc] = (float)tile8[d * 612 + (r0 + rr) * 34 + col + cc];
#pragma unroll
        for (int k = 0; k < 16; k++) {
            const float* wp = wsh + (k * 16 + d) * 9;
            float w0 = wp[0], w1v = wp[1], w2v = wp[2];
            float w3 = wp[3], w4  = wp[4], w5  = wp[5];
            float w6 = wp[6], w7  = wp[7], w8  = wp[8];
#pragma unroll
            for (int rr = 0; rr < 4; rr++) {
                float a = acc[k][rr];
                a = fmaf(w0, xr[rr][0],     a);
                a = fmaf(w1v, xr[rr][1],    a);
                a = fmaf(w2v, xr[rr][2],    a);
                a = fmaf(w3, xr[rr + 1][0], a);
                a = fmaf(w4, xr[rr + 1][1], a);
                a = fmaf(w5, xr[rr + 1][2], a);
                a = fmaf(w6, xr[rr + 2][0], a);
                a = fmaf(w7, xr[rr + 2][1], a);
                a = fmaf(w8, xr[rr + 2][2], a);
                acc[k][rr] = a;
            }
        }
    }
    int nb = ns & 15, nn = ns >> 4;
    // ---- conv2 store + stats ----
    {
        float* op = g_c2b + ns * 16384;
        float sk[16], qk[16];
#pragma unroll
        for (int k = 0; k < 16; k++) {
            float s = 0.f, q = 0.f;
#pragma unroll
            for (int rr = 0; rr < 4; rr++) {
                float a = acc[k][rr];
                op[k * 1024 + (h0 + r0 + rr) * 32 + col] = a;
                s += a; q += a * a;
            }
            sk[k] = s; qk[k] = q;
        }
#pragma unroll
        for (int k = 0; k < 16; k++)
#pragma unroll
            for (int o = 16; o > 0; o >>= 1) {
                sk[k] += __shfl_down_sync(0xffffffffu, sk[k], o);
                qk[k] += __shfl_down_sync(0xffffffffu, qk[k], o);
            }
        if ((tid & 31) == 0) {
            int w = tid >> 5;
#pragma unroll
            for (int k = 0; k < 16; k++) { R[k][0][w] = sk[k]; R[k][1][w] = qk[k]; }
        }
        __syncthreads();
        if (tid < 32) {
            int k = tid >> 1, j = tid & 1;
            float a = 0.f;
#pragma unroll
            for (int w = 0; w < 4; w++) a += R[k][j][w];
            int idx = (nb * 16 + k) * 64 + nn * 2 + (blk & 1);
            if (j == 0) g_ps_c2[idx] = a;
            else        g_pq_c2[idx] = a;
        }
        __syncthreads();
    }
    // ---- conv1 (reuse tile + acc registers) ----
#pragma unroll
    for (int k = 0; k < 16; k++) {
        float bv = bsh1[k];
#pragma unroll
        for (int rr = 0; rr < 4; rr++) acc[k][rr] = bv;
    }
    for (int d = 0; d < 16; d++) {
        float ce[4];
#pragma unroll
        for (int rr = 0; rr < 4; rr++) ce[rr] = (float)tile8[d * 612 + (r0 + rr + 1) * 34 + col + 1];
#pragma unroll
        for (int k = 0; k < 16; k++) {
            float wv = w1sh[k * 16 + d];
#pragma unroll
            for (int rr = 0; rr < 4; rr++) acc[k][rr] = fmaf(wv, ce[rr], acc[k][rr]);
        }
    }
    {
        float* op = g_c1b + ns * 16384;
        float sk[16], qk[16];
#pragma unroll
        for (int k = 0; k < 16; k++) {
            float s = 0.f, q = 0.f;
#pragma unroll
            for (int rr = 0; rr < 4; rr++) {
                float a = acc[k][rr];
                op[k * 1024 + (h0 + r0 + rr) * 32 + col] = a;
                s += a; q += a * a;
            }
            sk[k] = s; qk[k] = q;
        }
#pragma unroll
        for (int k = 0; k < 16; k++)
#pragma unroll
            for (int o = 16; o > 0; o >>= 1) {
                sk[k] += __shfl_down_sync(0xffffffffu, sk[k], o);
                qk[k] += __shfl_down_sync(0xffffffffu, qk[k], o);
            }
        if ((tid & 31) == 0) {
            int w = tid >> 5;
#pragma unroll
            for (int k = 0; k < 16; k++) { R[k][0][w] = sk[k]; R[k][1][w] = qk[k]; }
        }
        __syncthreads();
        if (tid < 32) {
            int k = tid >> 1, j = tid & 1;
            float a = 0.f;
#pragma unroll
            for (int w = 0; w < 4; w++) a += R[k][j][w];
            int idx = (nb * 16 + k) * 64 + nn * 2 + (blk & 1);
            if (j == 0) g_ps_c1[idx] = a;
            else        g_pq_c1[idx] = a;
        }
    }
}

// ---------------- final: inline fold3 + BN-apply x3 + sum (float4) ----------------
__global__ void final_kernel(float4* __restrict__ out,
                             const float* __restrict__ gi, const float* __restrict__ bi,
                             const float* __restrict__ g1, const float* __restrict__ b1,
                             const float* __restrict__ g2, const float* __restrict__ b2) {
    int tid = threadIdx.x;
    int c = blockIdx.x & 255;       // each block serves exactly one channel
    __shared__ float A6[6];
    int w = tid >> 5, lane = tid & 31;
    if (w < 3) {
        float s, q;
        if (w == 0) {
            s = g_ps_inv[c * 32 + lane];
            q = g_pq_inv[c * 32 + lane];
        } else if (w == 1) {
            s = g_ps_c1[c * 64 + lane] + g_ps_c1[c * 64 + 32 + lane];
            q = g_pq_c1[c * 64 + lane] + g_pq_c1[c * 64 + 32 + lane];
        } else {
            s = g_ps_c2[c * 64 + lane] + g_ps_c2[c * 64 + 32 + lane];
            q = g_pq_c2[c * 64 + lane] + g_pq_c2[c * 64 + 32 + lane];
        }
#pragma unroll
        for (int o = 16; o > 0; o >>= 1) {
            s += __shfl_down_sync(0xffffffffu, s, o);
            q += __shfl_down_sync(0xffffffffu, q, o);
        }
        if (lane == 0) {
            float inv = 1.f / 32768.f;
            float mean = s * inv, msq = q * inv;
            float var = msq - mean * mean; if (var < 0.f) var = 0.f;
            const float* gp = (w == 0) ? gi : (w == 1) ? g1 : g2;
            const float* bp = (w == 0) ? bi : (w == 1) ? b1 : b2;
            float a = gp[c] / sqrtf(var + 1e-5f);
            A6[w * 2] = a; A6[w * 2 + 1] = bp[c] - mean * a;
        }
    }
    __syncthreads();
    float ar = A6[0], br = A6[1];
    float a1 = A6[2], b1v = A6[3];
    float a2 = A6[4], b2v = A6[5];
    int i4 = blockIdx.x * 256 + tid;
    float4 r = ((const float4*)g_rec)[i4];
    float4 u = ((const float4*)g_c1b)[i4];
    float4 v = ((const float4*)g_c2b)[i4];
    float4 o;
    o.x = r.x * ar + br + u.x * a1 + b1v + v.x * a2 + b2v;
    o.y = r.y * ar + br + u.y * a1 + b1v + v.y * a2 + b2v;
    o.z = r.z * ar + br + u.z * a1 + b1v + v.z * a2 + b2v;
    o.w = r.w * ar + br + u.w * a1 + b1v + v.w * a2 + b2v;
    out[i4] = o;
}

// ---------------- host ----------------
extern "C" void kernel_launch(void* const* d_in, const int* in_sizes, int n_in,
                              void* d_out, int out_size) {
    const float* x    = (const float*)d_in[0];
    const float* hw   = (const float*)d_in[1];
    const float* w1   = (const float*)d_in[2];
    const float* b1   = (const float*)d_in[3];
    const float* w2   = (const float*)d_in[4];
    const float* b2   = (const float*)d_in[5];
    const float* gfwd = (const float*)d_in[6];
    const float* bfwd = (const float*)d_in[7];
    const float* gmul = (const float*)d_in[8];
    const float* bmul = (const float*)d_in[9];
    const float* ginv = (const float*)d_in[10];
    const float* binv = (const float*)d_in[11];
    const float* gc1  = (const float*)d_in[12];
    const float* bc1  = (const float*)d_in[13];
    const float* gc2  = (const float*)d_in[14];
    const float* bc2  = (const float*)d_in[15];
    float* out = (float*)d_out;

    lif_h1_kernel<<<2048, 256>>>((const float4*)x);
    stats_h2_kernel<<<1024, 256>>>(gfwd, bfwd);
    mixinv_kernel<<<512, 256>>>(hw, gfwd, bfwd, gmul, bmul);
    conv_kernel<<<1024, 128>>>(w2, b2, w1, b1);
    final_kernel<<<8192, 256>>>((float4*)out, ginv, binv, gc1, bc1, gc2, bc2);
}